// round 9
// baseline (speedup 1.0000x reference)
#include <cuda_runtime.h>

// Problem constants: B=8192, T=64, D=512
#define BB 8192
#define TT 64
#define DD 512

__device__ __forceinline__ float warp_reduce_sum(float v) {
    #pragma unroll
    for (int off = 16; off > 0; off >>= 1)
        v += __shfl_xor_sync(0xFFFFFFFFu, v, off);
    return v;
}

__global__ __launch_bounds__(256)
void sdpa_decode_kernel(const float* __restrict__ q,
                        const float* __restrict__ k,
                        const float* __restrict__ v,
                        const int*   __restrict__ pad_mask,
                        float* __restrict__ out,       // [B, D]
                        float* __restrict__ attn_out)  // [B, T]
{
    const int b    = blockIdx.x;
    const int tid  = threadIdx.x;
    const int warp = tid >> 5;
    const int lane = tid & 31;

    const float INV_TEMP  = 0.04419417382415922f;   // 1/sqrt(512)
    const float MASK_FILL = -1000.0f;

    __shared__ float4 qs[DD / 4];     // q row: 128 float4
    __shared__ float  s_logit[TT];
    __shared__ int    s_mask[TT];
    __shared__ float  s_p[TT];        // compacted probabilities
    __shared__ int    s_t[TT];        // compacted active t indices
    __shared__ int    s_n;

    // ---- load q[b] and pad_mask[b] into shared ----
    const float4* q4 = reinterpret_cast<const float4*>(q + (size_t)b * DD);
    if (tid < DD / 4) qs[tid] = q4[tid];
    if (tid < TT)     s_mask[tid] = pad_mask[(size_t)b * TT + tid];
    __syncthreads();

    // ---- compact active rows from mask (warp 0) ----
    if (warp == 0) {
        int m0 = s_mask[lane];
        int m1 = s_mask[lane + 32];
        unsigned b0 = __ballot_sync(0xFFFFFFFFu, m0 == 0);
        unsigned b1 = __ballot_sync(0xFFFFFFFFu, m1 == 0);
        int n0 = __popc(b0);
        unsigned lt = (1u << lane) - 1u;
        if (!m0) s_t[__popc(b0 & lt)]      = lane;
        if (!m1) s_t[n0 + __popc(b1 & lt)] = lane + 32;
        if (lane == 0) s_n = n0 + __popc(b1);
    }
    __syncthreads();
    const int na = s_n;

    // ---- QK^T: 4 list entries per warp per pass -> 16 independent LDG.128 ----
    const float4* kbase = reinterpret_cast<const float4*>(k + (size_t)b * TT * DD);
    for (int base = 0; base < na; base += 32) {
        const int e0 = base + warp;
        const int e1 = e0 + 8;
        const int e2 = e0 + 16;
        const int e3 = e0 + 24;
        const bool g0 = e0 < na, g1 = e1 < na, g2 = e2 < na, g3 = e3 < na;
        const int t0 = g0 ? s_t[e0] : 0;
        const int t1 = g1 ? s_t[e1] : 0;
        const int t2 = g2 ? s_t[e2] : 0;
        const int t3 = g3 ? s_t[e3] : 0;
        const float4* k0 = kbase + (size_t)t0 * (DD / 4);
        const float4* k1 = kbase + (size_t)t1 * (DD / 4);
        const float4* k2 = kbase + (size_t)t2 * (DD / 4);
        const float4* k3 = kbase + (size_t)t3 * (DD / 4);
        float a0 = 0.0f, a1 = 0.0f, a2 = 0.0f, a3 = 0.0f;
        #pragma unroll
        for (int j = 0; j < 4; j++) {
            const int idx = lane + j * 32;      // 0..127
            const float4 qv = qs[idx];
            if (g0) { float4 kv = k0[idx];
                      a0 += kv.x*qv.x + kv.y*qv.y + kv.z*qv.z + kv.w*qv.w; }
            if (g1) { float4 kv = k1[idx];
                      a1 += kv.x*qv.x + kv.y*qv.y + kv.z*qv.z + kv.w*qv.w; }
            if (g2) { float4 kv = k2[idx];
                      a2 += kv.x*qv.x + kv.y*qv.y + kv.z*qv.z + kv.w*qv.w; }
            if (g3) { float4 kv = k3[idx];
                      a3 += kv.x*qv.x + kv.y*qv.y + kv.z*qv.z + kv.w*qv.w; }
        }
        // 4 independent reduce chains (interleaved by the scheduler)
        a0 = warp_reduce_sum(a0);
        a1 = warp_reduce_sum(a1);
        a2 = warp_reduce_sum(a2);
        a3 = warp_reduce_sum(a3);
        if (lane == 0) {
            if (g0) s_logit[t0] = a0;
            if (g1) s_logit[t1] = a1;
            if (g2) s_logit[t2] = a2;
            if (g3) s_logit[t3] = a3;
        }
    }
    __syncthreads();

    // ---- masked softmax (warp 0, 2 values/lane) + probability compaction ----
    if (warp == 0) {
        int m0 = s_mask[lane];
        int m1 = s_mask[lane + 32];
        float v0 = m0 ? MASK_FILL : s_logit[lane]      * INV_TEMP;
        float v1 = m1 ? MASK_FILL : s_logit[lane + 32] * INV_TEMP;

        float m = fmaxf(v0, v1);
        #pragma unroll
        for (int off = 16; off > 0; off >>= 1)
            m = fmaxf(m, __shfl_xor_sync(0xFFFFFFFFu, m, off));

        float e0 = __expf(v0 - m);   // underflows to exact 0 for masked (matches ref)
        float e1 = __expf(v1 - m);
        float ssum = warp_reduce_sum(e0 + e1);
        float inv = 1.0f / ssum;
        float p0 = e0 * inv;
        float p1 = e1 * inv;

        attn_out[(size_t)b * TT + lane]      = p0;
        attn_out[(size_t)b * TT + lane + 32] = p1;

        // probabilities into compacted slots (same ballot math as list build)
        unsigned b0 = __ballot_sync(0xFFFFFFFFu, m0 == 0);
        unsigned b1 = __ballot_sync(0xFFFFFFFFu, m1 == 0);
        int n0 = __popc(b0);
        unsigned lt = (1u << lane) - 1u;
        if (!m0) s_p[__popc(b0 & lt)]      = p0;
        if (!m1) s_p[n0 + __popc(b1 & lt)] = p1;

        // all-masked edge case: uniform 1/64 over ALL rows
        if (n0 + __popc(b1) == 0) {
            s_t[lane]      = lane;      s_p[lane]      = p0;  // p0 == 1/64
            s_t[lane + 32] = lane + 32; s_p[lane + 32] = p1;
            if (lane == 0) s_n = TT;
        }
    }
    __syncthreads();

    // ---- P·V over ACTIVE rows; 256 threads x float2, unroll x8, int offsets ----
    const float2* vbase = reinterpret_cast<const float2*>(v + (size_t)b * TT * DD);
    const int d2 = tid;                 // float2 index 0..255
    const int n  = s_n;
    float2 acc = make_float2(0.0f, 0.0f);

    int i = 0;
    for (; i + 8 <= n; i += 8) {
        float p0 = s_p[i],   p1 = s_p[i+1], p2 = s_p[i+2], p3 = s_p[i+3];
        float p4 = s_p[i+4], p5 = s_p[i+5], p6 = s_p[i+6], p7 = s_p[i+7];
        int o0 = s_t[i]   * (DD / 2) + d2;
        int o1 = s_t[i+1] * (DD / 2) + d2;
        int o2 = s_t[i+2] * (DD / 2) + d2;
        int o3 = s_t[i+3] * (DD / 2) + d2;
        int o4 = s_t[i+4] * (DD / 2) + d2;
        int o5 = s_t[i+5] * (DD / 2) + d2;
        int o6 = s_t[i+6] * (DD / 2) + d2;
        int o7 = s_t[i+7] * (DD / 2) + d2;
        float2 v0 = vbase[o0], v1 = vbase[o1], v2 = vbase[o2], v3 = vbase[o3];
        float2 v4 = vbase[o4], v5 = vbase[o5], v6 = vbase[o6], v7 = vbase[o7];
        acc.x += p0 * v0.x; acc.y += p0 * v0.y;
        acc.x += p1 * v1.x; acc.y += p1 * v1.y;
        acc.x += p2 * v2.x; acc.y += p2 * v2.y;
        acc.x += p3 * v3.x; acc.y += p3 * v3.y;
        acc.x += p4 * v4.x; acc.y += p4 * v4.y;
        acc.x += p5 * v5.x; acc.y += p5 * v5.y;
        acc.x += p6 * v6.x; acc.y += p6 * v6.y;
        acc.x += p7 * v7.x; acc.y += p7 * v7.y;
    }
    for (; i + 4 <= n; i += 4) {
        float pa = s_p[i],   pb = s_p[i+1], pc = s_p[i+2], pd = s_p[i+3];
        int oa = s_t[i]   * (DD / 2) + d2;
        int ob = s_t[i+1] * (DD / 2) + d2;
        int oc = s_t[i+2] * (DD / 2) + d2;
        int od = s_t[i+3] * (DD / 2) + d2;
        float2 va = vbase[oa], vb = vbase[ob], vc = vbase[oc], vd = vbase[od];
        acc.x += pa * va.x; acc.y += pa * va.y;
        acc.x += pb * vb.x; acc.y += pb * vb.y;
        acc.x += pc * vc.x; acc.y += pc * vc.y;
        acc.x += pd * vd.x; acc.y += pd * vd.y;
    }
    for (; i < n; i++) {
        float  p  = s_p[i];
        float2 vv = vbase[s_t[i] * (DD / 2) + d2];
        acc.x += p * vv.x; acc.y += p * vv.y;
    }
    reinterpret_cast<float2*>(out + (size_t)b * DD)[d2] = acc;
}

extern "C" void kernel_launch(void* const* d_in, const int* in_sizes, int n_in,
                              void* d_out, int out_size) {
    const float* q        = (const float*)d_in[0];   // [B, D]
    const float* k        = (const float*)d_in[1];   // [B, T, D]
    const float* v        = (const float*)d_in[2];   // [B, T, D]
    const int*   pad_mask = (const int*)  d_in[3];   // [B, T]

    float* out      = (float*)d_out;                   // [B,1,D]
    float* attn_out = (float*)d_out + (size_t)BB * DD; // [B,1,T]

    sdpa_decode_kernel<<<BB, 256>>>(q, k, v, pad_mask, out, attn_out);
}

// round 10
// speedup vs baseline: 1.0213x; 1.0213x over previous
#include <cuda_runtime.h>

// Problem constants: B=8192, T=64, D=512
#define BB 8192
#define TT 64
#define DD 512
#define NWPB 4          // warps per block; one warp per batch row

#define FULLM 0xFFFFFFFFu

__device__ __forceinline__ float warp_reduce_sum(float v) {
    #pragma unroll
    for (int off = 16; off > 0; off >>= 1)
        v += __shfl_xor_sync(FULLM, v, off);
    return v;
}

__device__ __forceinline__ float dot4(float4 a, float4 b) {
    return a.x * b.x + a.y * b.y + a.z * b.z + a.w * b.w;
}

__global__ __launch_bounds__(128)
void sdpa_decode_kernel(const float* __restrict__ q,
                        const float* __restrict__ k,
                        const float* __restrict__ v,
                        const int*   __restrict__ pad_mask,
                        float* __restrict__ out,       // [B, D]
                        float* __restrict__ attn_out)  // [B, T]
{
    const int warp = threadIdx.x >> 5;
    const int lane = threadIdx.x & 31;
    const int b    = blockIdx.x * NWPB + warp;   // one warp owns one batch row

    const float INV_TEMP  = 0.04419417382415922f;   // 1/sqrt(512)
    const float MASK_FILL = -1000.0f;

    // ---- q row into registers: 16 floats/lane, layout idx = lane + j*32 ----
    const float4* qrow = reinterpret_cast<const float4*>(q + (size_t)b * DD);
    const float4 q0 = qrow[lane];
    const float4 q1 = qrow[lane + 32];
    const float4 q2 = qrow[lane + 64];
    const float4 q3 = qrow[lane + 96];

    // ---- mask: lane holds t=lane and t=lane+32; active set as 64-bit reg mask ----
    const int mm0 = pad_mask[(size_t)b * TT + lane];
    const int mm1 = pad_mask[(size_t)b * TT + lane + 32];
    const unsigned am0 = __ballot_sync(FULLM, mm0 == 0);
    const unsigned am1 = __ballot_sync(FULLM, mm1 == 0);
    const unsigned long long act =
        (unsigned long long)am0 | ((unsigned long long)am1 << 32);

    // ---- QK^T: stream active K rows in pairs (8 independent LDG.128) ----
    const float4* kbase = reinterpret_cast<const float4*>(k + (size_t)b * TT * DD);
    float lg0 = 0.0f, lg1 = 0.0f;      // logits owned by this lane (t=lane, t=lane+32)
    {
        unsigned long long rem = act;
        while (rem) {
            const int t0 = __ffsll((long long)rem) - 1;
            rem &= rem - 1ull;
            if (rem) {
                const int t1 = __ffsll((long long)rem) - 1;
                rem &= rem - 1ull;
                const float4* ka = kbase + (size_t)t0 * (DD / 4);
                const float4* kb = kbase + (size_t)t1 * (DD / 4);
                float4 a0 = ka[lane], a1 = ka[lane + 32], a2 = ka[lane + 64], a3 = ka[lane + 96];
                float4 c0 = kb[lane], c1 = kb[lane + 32], c2 = kb[lane + 64], c3 = kb[lane + 96];
                float da = dot4(a0, q0) + dot4(a1, q1) + dot4(a2, q2) + dot4(a3, q3);
                float db = dot4(c0, q0) + dot4(c1, q1) + dot4(c2, q2) + dot4(c3, q3);
                da = warp_reduce_sum(da);
                db = warp_reduce_sum(db);
                if (lane == (t0 & 31)) { if (t0 < 32) lg0 = da; else lg1 = da; }
                if (lane == (t1 & 31)) { if (t1 < 32) lg0 = db; else lg1 = db; }
            } else {
                const float4* ka = kbase + (size_t)t0 * (DD / 4);
                float4 a0 = ka[lane], a1 = ka[lane + 32], a2 = ka[lane + 64], a3 = ka[lane + 96];
                float da = dot4(a0, q0) + dot4(a1, q1) + dot4(a2, q2) + dot4(a3, q3);
                da = warp_reduce_sum(da);
                if (lane == (t0 & 31)) { if (t0 < 32) lg0 = da; else lg1 = da; }
            }
        }
    }

    // ---- per-warp masked softmax (no barriers) ----
    float v0 = mm0 ? MASK_FILL : lg0 * INV_TEMP;
    float v1 = mm1 ? MASK_FILL : lg1 * INV_TEMP;
    float m = fmaxf(v0, v1);
    #pragma unroll
    for (int off = 16; off > 0; off >>= 1)
        m = fmaxf(m, __shfl_xor_sync(FULLM, m, off));
    float e0 = __expf(v0 - m);          // exact 0 for masked rows (matches reference)
    float e1 = __expf(v1 - m);
    float ssum = warp_reduce_sum(e0 + e1);
    float inv = 1.0f / ssum;
    float p0 = e0 * inv;
    float p1 = e1 * inv;

    attn_out[(size_t)b * TT + lane]      = p0;
    attn_out[(size_t)b * TT + lane + 32] = p1;

    // ---- P·V: stream V rows in pairs; probs broadcast via shfl ----
    // all-masked edge case: act==0 -> p==1/64 everywhere, iterate ALL rows
    const unsigned long long pvmask = act ? act : ~0ull;
    const float4* vbase = reinterpret_cast<const float4*>(v + (size_t)b * TT * DD);
    float4 acc0 = make_float4(0.f, 0.f, 0.f, 0.f);
    float4 acc1 = acc0, acc2 = acc0, acc3 = acc0;
    {
        unsigned long long rem = pvmask;
        while (rem) {
            const int t0 = __ffsll((long long)rem) - 1;
            rem &= rem - 1ull;
            if (rem) {
                const int t1 = __ffsll((long long)rem) - 1;
                rem &= rem - 1ull;
                const float pa = (t0 < 32) ? __shfl_sync(FULLM, p0, t0)
                                           : __shfl_sync(FULLM, p1, t0 - 32);
                const float pb = (t1 < 32) ? __shfl_sync(FULLM, p0, t1)
                                           : __shfl_sync(FULLM, p1, t1 - 32);
                const float4* va = vbase + (size_t)t0 * (DD / 4);
                const float4* vb = vbase + (size_t)t1 * (DD / 4);
                float4 x0 = va[lane], x1 = va[lane + 32], x2 = va[lane + 64], x3 = va[lane + 96];
                float4 y0 = vb[lane], y1 = vb[lane + 32], y2 = vb[lane + 64], y3 = vb[lane + 96];
                acc0.x += pa * x0.x + pb * y0.x; acc0.y += pa * x0.y + pb * y0.y;
                acc0.z += pa * x0.z + pb * y0.z; acc0.w += pa * x0.w + pb * y0.w;
                acc1.x += pa * x1.x + pb * y1.x; acc1.y += pa * x1.y + pb * y1.y;
                acc1.z += pa * x1.z + pb * y1.z; acc1.w += pa * x1.w + pb * y1.w;
                acc2.x += pa * x2.x + pb * y2.x; acc2.y += pa * x2.y + pb * y2.y;
                acc2.z += pa * x2.z + pb * y2.z; acc2.w += pa * x2.w + pb * y2.w;
                acc3.x += pa * x3.x + pb * y3.x; acc3.y += pa * x3.y + pb * y3.y;
                acc3.z += pa * x3.z + pb * y3.z; acc3.w += pa * x3.w + pb * y3.w;
            } else {
                const float pa = (t0 < 32) ? __shfl_sync(FULLM, p0, t0)
                                           : __shfl_sync(FULLM, p1, t0 - 32);
                const float4* va = vbase + (size_t)t0 * (DD / 4);
                float4 x0 = va[lane], x1 = va[lane + 32], x2 = va[lane + 64], x3 = va[lane + 96];
                acc0.x += pa * x0.x; acc0.y += pa * x0.y; acc0.z += pa * x0.z; acc0.w += pa * x0.w;
                acc1.x += pa * x1.x; acc1.y += pa * x1.y; acc1.z += pa * x1.z; acc1.w += pa * x1.w;
                acc2.x += pa * x2.x; acc2.y += pa * x2.y; acc2.z += pa * x2.z; acc2.w += pa * x2.w;
                acc3.x += pa * x3.x; acc3.y += pa * x3.y; acc3.z += pa * x3.z; acc3.w += pa * x3.w;
            }
        }
    }

    float4* orow = reinterpret_cast<float4*>(out + (size_t)b * DD);
    orow[lane]      = acc0;
    orow[lane + 32] = acc1;
    orow[lane + 64] = acc2;
    orow[lane + 96] = acc3;
}

extern "C" void kernel_launch(void* const* d_in, const int* in_sizes, int n_in,
                              void* d_out, int out_size) {
    const float* q        = (const float*)d_in[0];   // [B, D]
    const float* k        = (const float*)d_in[1];   // [B, T, D]
    const float* v        = (const float*)d_in[2];   // [B, T, D]
    const int*   pad_mask = (const int*)  d_in[3];   // [B, T]

    float* out      = (float*)d_out;                   // [B,1,D]
    float* attn_out = (float*)d_out + (size_t)BB * DD; // [B,1,T]

    sdpa_decode_kernel<<<BB / NWPB, 32 * NWPB>>>(q, k, v, pad_mask, out, attn_out);
}